// round 3
// baseline (speedup 1.0000x reference)
#include <cuda_runtime.h>

#define EN 131072
#define NN 4096
#define BB 4
#define CC 128
#define OO 127

// ---------------- scratch (device globals; no allocation) ----------------
__device__ float g_xT[BB * NN * CC];      // x transposed: [b][n][c]   (8 MB)
__device__ float g_U[BB * NN * 256];      // [cnt*xT | S] : [b][n][256] (16 MB)
__device__ float g_Wcat[128 * 256];       // [W0 | W1], row 127 = zeros (128 KB)
__device__ int   g_cnt[NN];               // histogram of idx_i
__device__ int   g_deg[NN];               // histogram of idx_j
__device__ int   g_cur[NN];               // CSR fill cursors
__device__ int   g_off[NN + 1];           // CSR row offsets
__device__ int   g_dst[EN];               // idx_j grouped by idx_i

// ---------------- packed f32x2 helpers ----------------
__device__ __forceinline__ unsigned long long rep2(float a) {
    unsigned long long r;
    asm("mov.b64 %0, {%1, %1};" : "=l"(r) : "f"(a));
    return r;
}
__device__ __forceinline__ void fma2(unsigned long long& d,
                                     unsigned long long a,
                                     unsigned long long b) {
    asm("fma.rn.f32x2 %0, %1, %2, %0;" : "+l"(d) : "l"(a), "l"(b));
}
__device__ __forceinline__ float2 unpack2(unsigned long long v) {
    float2 r;
    asm("mov.b64 {%0, %1}, %2;" : "=f"(r.x), "=f"(r.y) : "l"(v));
    return r;
}

// ---------------- kernels ----------------
__global__ void k_zero() {
    int t = blockIdx.x * blockDim.x + threadIdx.x;
    if (t < NN) g_cnt[t] = 0;
    else if (t < 2 * NN) g_deg[t - NN] = 0;
}

__global__ void k_hist(const int* __restrict__ ii, const int* __restrict__ jj) {
    int e = blockIdx.x * blockDim.x + threadIdx.x;
    if (e < EN) {
        atomicAdd(&g_cnt[ii[e]], 1);
        atomicAdd(&g_deg[jj[e]], 1);
    }
}

// exclusive scan of g_cnt (4096 bins) in a single 1024-thread block
__global__ void k_scan() {
    __shared__ int sm[1024];
    int tid = threadIdx.x;
    int v0 = g_cnt[4 * tid + 0];
    int v1 = g_cnt[4 * tid + 1];
    int v2 = g_cnt[4 * tid + 2];
    int v3 = g_cnt[4 * tid + 3];
    sm[tid] = v0 + v1 + v2 + v3;
    __syncthreads();
    for (int d = 1; d < 1024; d <<= 1) {
        int t = (tid >= d) ? sm[tid - d] : 0;
        __syncthreads();
        sm[tid] += t;
        __syncthreads();
    }
    int base = tid ? sm[tid - 1] : 0;
    int o0 = base;
    int o1 = base + v0;
    int o2 = o1 + v1;
    int o3 = o2 + v2;
    g_off[4 * tid + 0] = o0;  g_cur[4 * tid + 0] = o0;
    g_off[4 * tid + 1] = o1;  g_cur[4 * tid + 1] = o1;
    g_off[4 * tid + 2] = o2;  g_cur[4 * tid + 2] = o2;
    g_off[4 * tid + 3] = o3;  g_cur[4 * tid + 3] = o3;
    if (tid == 1023) g_off[NN] = sm[1023];
}

__global__ void k_csr(const int* __restrict__ ii, const int* __restrict__ jj) {
    int e = blockIdx.x * blockDim.x + threadIdx.x;
    if (e < EN) {
        int p = atomicAdd(&g_cur[ii[e]], 1);
        g_dst[p] = jj[e];
    }
}

// build concatenated weight matrix [W0 | W1], zero-pad row 127
__global__ void k_wcat(const float* __restrict__ W) {
    int t = blockIdx.x * blockDim.x + threadIdx.x;  // 0..16383
    int o = t >> 7;
    int c = t & 127;
    if (o < OO) {
        g_Wcat[o * 256 + c]       = W[(o * 128 + c) * 2 + 0];
        g_Wcat[o * 256 + 128 + c] = W[(o * 128 + c) * 2 + 1];
    } else {
        g_Wcat[o * 256 + c] = 0.0f;
        g_Wcat[o * 256 + 128 + c] = 0.0f;
    }
}

// transpose x[b][c][n] -> xT[b][n][c]; also write U[b][n][c] = cnt_i[n]*xT
__global__ void k_transpose(const float* __restrict__ x) {
    __shared__ float tile[32][33];
    int b = blockIdx.z;
    int c0 = blockIdx.y * 32;
    int n0 = blockIdx.x * 32;
    int tx = threadIdx.x, ty = threadIdx.y;
#pragma unroll
    for (int r = 0; r < 4; r++) {
        int c = c0 + ty + 8 * r;
        tile[ty + 8 * r][tx] = x[((size_t)b * CC + c) * NN + n0 + tx];
    }
    __syncthreads();
#pragma unroll
    for (int r = 0; r < 4; r++) {
        int n = n0 + ty + 8 * r;
        float v = tile[tx][ty + 8 * r];
        float cf = (float)g_cnt[n];
        g_xT[((size_t)b * NN + n) * CC + c0 + tx] = v;
        g_U[((size_t)b * NN + n) * 256 + c0 + tx] = v * cf;
    }
}

// gather: S[b][n][:] = sum over CSR neighbors j of xT[b][j][:]
// one block per n; warp w handles batch w; lane holds a float4 (4 channels)
__global__ void k_gather() {
    int n = blockIdx.x;
    int w = threadIdx.x >> 5;
    int lane = threadIdx.x & 31;
    int beg = g_off[n], end = g_off[n + 1];
    const float4* base = ((const float4*)g_xT) + (size_t)w * NN * 32;
    float4 acc = make_float4(0.f, 0.f, 0.f, 0.f);
    int k = beg;
    for (; k + 4 <= end; k += 4) {
        int j0 = g_dst[k + 0];
        int j1 = g_dst[k + 1];
        int j2 = g_dst[k + 2];
        int j3 = g_dst[k + 3];
        float4 v0 = base[(size_t)j0 * 32 + lane];
        float4 v1 = base[(size_t)j1 * 32 + lane];
        float4 v2 = base[(size_t)j2 * 32 + lane];
        float4 v3 = base[(size_t)j3 * 32 + lane];
        acc.x += (v0.x + v1.x) + (v2.x + v3.x);
        acc.y += (v0.y + v1.y) + (v2.y + v3.y);
        acc.z += (v0.z + v1.z) + (v2.z + v3.z);
        acc.w += (v0.w + v1.w) + (v2.w + v3.w);
    }
    for (; k < end; k++) {
        int j = g_dst[k];
        float4 v = base[(size_t)j * 32 + lane];
        acc.x += v.x; acc.y += v.y; acc.z += v.z; acc.w += v.w;
    }
    ((float4*)(g_U + ((size_t)w * NN + n) * 256 + 128))[lane] = acc;
}

// GEMM: y[b][o][n] = (sum_k U[b][n][k]*Wcat[o][k] + cnt[n]*bias[o]) / max(deg[n],1)
// channel 127 = deg[n]. BM=64 (n), all 128 o per block, K=256, BK=16, 256 thr.
// thread: tx=tid&15 -> 4 consecutive n; ty=tid>>4 -> 8 consecutive o.
__global__ void __launch_bounds__(256) k_gemm(const float* __restrict__ bias,
                                              float* __restrict__ out) {
    __shared__ __align__(16) float As[16][64];
    __shared__ __align__(16) float Bs[16][128];
    int b = blockIdx.y;
    int n0 = blockIdx.x * 64;
    int tid = threadIdx.x;
    int tx = tid & 15;
    int ty = tid >> 4;

    unsigned long long acc[4][4];
#pragma unroll
    for (int i = 0; i < 4; i++)
#pragma unroll
        for (int p = 0; p < 4; p++) acc[i][p] = 0ull;

    const float* Ub = g_U + ((size_t)b * NN + n0) * 256;

    for (int kk = 0; kk < 256; kk += 16) {
        // load A tile (transposed into As[k][m]) -- conflict-free STS.32
        {
            int m = tid & 63;
            int kq = tid >> 6;
            float4 v = *(const float4*)(Ub + (size_t)m * 256 + kk + kq * 4);
            As[kq * 4 + 0][m] = v.x;
            As[kq * 4 + 1][m] = v.y;
            As[kq * 4 + 2][m] = v.z;
            As[kq * 4 + 3][m] = v.w;
        }
        // load B tile (Wcat transposed into Bs[k][o])
#pragma unroll
        for (int r = 0; r < 2; r++) {
            int idx = tid + r * 256;
            int o = idx & 127;
            int kq = idx >> 7;
            float4 v = *(const float4*)(g_Wcat + o * 256 + kk + kq * 4);
            Bs[kq * 4 + 0][o] = v.x;
            Bs[kq * 4 + 1][o] = v.y;
            Bs[kq * 4 + 2][o] = v.z;
            Bs[kq * 4 + 3][o] = v.w;
        }
        __syncthreads();
#pragma unroll
        for (int k = 0; k < 16; k++) {
            float4 av = *(const float4*)&As[k][tx * 4];
            ulonglong2 bv0 = *(const ulonglong2*)&Bs[k][ty * 8];
            ulonglong2 bv1 = *(const ulonglong2*)&Bs[k][ty * 8 + 4];
            unsigned long long a0 = rep2(av.x);
            unsigned long long a1 = rep2(av.y);
            unsigned long long a2 = rep2(av.z);
            unsigned long long a3 = rep2(av.w);
            fma2(acc[0][0], a0, bv0.x); fma2(acc[0][1], a0, bv0.y);
            fma2(acc[0][2], a0, bv1.x); fma2(acc[0][3], a0, bv1.y);
            fma2(acc[1][0], a1, bv0.x); fma2(acc[1][1], a1, bv0.y);
            fma2(acc[1][2], a1, bv1.x); fma2(acc[1][3], a1, bv1.y);
            fma2(acc[2][0], a2, bv0.x); fma2(acc[2][1], a2, bv0.y);
            fma2(acc[2][2], a2, bv1.x); fma2(acc[2][3], a2, bv1.y);
            fma2(acc[3][0], a3, bv0.x); fma2(acc[3][1], a3, bv0.y);
            fma2(acc[3][2], a3, bv1.x); fma2(acc[3][3], a3, bv1.y);
        }
        __syncthreads();
    }

    // epilogue
    float f[4][8];
#pragma unroll
    for (int i = 0; i < 4; i++)
#pragma unroll
        for (int p = 0; p < 4; p++) {
            float2 u = unpack2(acc[i][p]);
            f[i][2 * p] = u.x;
            f[i][2 * p + 1] = u.y;
        }

    int nn0 = n0 + tx * 4;
    float inv[4], cf[4], dg[4];
#pragma unroll
    for (int i = 0; i < 4; i++) {
        int d = g_deg[nn0 + i];
        dg[i] = (float)d;
        inv[i] = 1.0f / (float)(d > 0 ? d : 1);
        cf[i] = (float)g_cnt[nn0 + i];
    }
#pragma unroll
    for (int p = 0; p < 8; p++) {
        int o = ty * 8 + p;
        float bi = (o < OO) ? bias[o] : 0.0f;
        float4 sv;
        if (o < OO) {
            sv.x = (f[0][p] + cf[0] * bi) * inv[0];
            sv.y = (f[1][p] + cf[1] * bi) * inv[1];
            sv.z = (f[2][p] + cf[2] * bi) * inv[2];
            sv.w = (f[3][p] + cf[3] * bi) * inv[3];
        } else {
            sv.x = dg[0]; sv.y = dg[1]; sv.z = dg[2]; sv.w = dg[3];
        }
        *(float4*)&out[((size_t)(b * 128 + o)) * NN + nn0] = sv;
    }
}

// ---------------- launch ----------------
extern "C" void kernel_launch(void* const* d_in, const int* in_sizes, int n_in,
                              void* d_out, int out_size) {
    const float* x = nullptr;
    const float* W = nullptr;
    const float* bias = nullptr;
    const int* ii = nullptr;
    const int* jj = nullptr;
    for (int i = 0; i < n_in; i++) {
        int s = in_sizes[i];
        if (s == BB * CC * NN) x = (const float*)d_in[i];
        else if (s == OO * CC * 2) W = (const float*)d_in[i];
        else if (s == OO) bias = (const float*)d_in[i];
        else if (s == EN) {
            if (!ii) ii = (const int*)d_in[i];
            else jj = (const int*)d_in[i];
        }
    }
    float* out = (float*)d_out;

    k_zero<<<32, 256>>>();
    k_hist<<<EN / 256, 256>>>(ii, jj);
    k_scan<<<1, 1024>>>();
    k_csr<<<EN / 256, 256>>>(ii, jj);
    k_wcat<<<64, 256>>>(W);
    k_transpose<<<dim3(NN / 32, CC / 32, BB), dim3(32, 8)>>>(x);
    k_gather<<<NN, 128>>>();
    k_gemm<<<dim3(NN / 64, BB), 256>>>(bias, out);
}

// round 4
// speedup vs baseline: 1.0083x; 1.0083x over previous
#include <cuda_runtime.h>

#define EN 131072
#define NN 4096
#define BB 4
#define CC 128
#define OO 127

// ---------------- scratch (device globals; no allocation) ----------------
__device__ float g_xT[BB * NN * CC];      // x transposed: [b][n][c]   (8 MB)
__device__ float g_U[BB * NN * 256];      // [cnt*xT | S] : [b][n][256] (16 MB)
__device__ float g_Wcat[128 * 256];       // [W0 | W1], row 127 = zeros (128 KB)
__device__ int   g_cnt[NN];               // histogram of idx_i
__device__ int   g_deg[NN];               // histogram of idx_j
__device__ int   g_cur[NN];               // CSR fill cursors
__device__ int   g_off[NN + 1];           // CSR row offsets
__device__ int   g_dst[EN];               // idx_j grouped by idx_i

// ---------------- packed f32x2 helpers ----------------
__device__ __forceinline__ unsigned long long rep2(float a) {
    unsigned long long r;
    asm("mov.b64 %0, {%1, %1};" : "=l"(r) : "f"(a));
    return r;
}
__device__ __forceinline__ void fma2(unsigned long long& d,
                                     unsigned long long a,
                                     unsigned long long b) {
    asm("fma.rn.f32x2 %0, %1, %2, %0;" : "+l"(d) : "l"(a), "l"(b));
}
__device__ __forceinline__ float2 unpack2(unsigned long long v) {
    float2 r;
    asm("mov.b64 {%0, %1}, %2;" : "=f"(r.x), "=f"(r.y) : "l"(v));
    return r;
}

// ---------------- kernels ----------------
__global__ void k_zero() {
    int t = blockIdx.x * blockDim.x + threadIdx.x;
    if (t < NN) g_cnt[t] = 0;
    else if (t < 2 * NN) g_deg[t - NN] = 0;
}

__global__ void k_hist(const int* __restrict__ ii, const int* __restrict__ jj) {
    int e = blockIdx.x * blockDim.x + threadIdx.x;
    if (e < EN) {
        atomicAdd(&g_cnt[ii[e]], 1);
        atomicAdd(&g_deg[jj[e]], 1);
    }
}

// exclusive scan of g_cnt (4096 bins) in a single 1024-thread block
__global__ void k_scan() {
    __shared__ int sm[1024];
    int tid = threadIdx.x;
    int v0 = g_cnt[4 * tid + 0];
    int v1 = g_cnt[4 * tid + 1];
    int v2 = g_cnt[4 * tid + 2];
    int v3 = g_cnt[4 * tid + 3];
    sm[tid] = v0 + v1 + v2 + v3;
    __syncthreads();
    for (int d = 1; d < 1024; d <<= 1) {
        int t = (tid >= d) ? sm[tid - d] : 0;
        __syncthreads();
        sm[tid] += t;
        __syncthreads();
    }
    int base = tid ? sm[tid - 1] : 0;
    int o0 = base;
    int o1 = base + v0;
    int o2 = o1 + v1;
    int o3 = o2 + v2;
    g_off[4 * tid + 0] = o0;  g_cur[4 * tid + 0] = o0;
    g_off[4 * tid + 1] = o1;  g_cur[4 * tid + 1] = o1;
    g_off[4 * tid + 2] = o2;  g_cur[4 * tid + 2] = o2;
    g_off[4 * tid + 3] = o3;  g_cur[4 * tid + 3] = o3;
    if (tid == 1023) g_off[NN] = sm[1023];
}

__global__ void k_csr(const int* __restrict__ ii, const int* __restrict__ jj) {
    int e = blockIdx.x * blockDim.x + threadIdx.x;
    if (e < EN) {
        int p = atomicAdd(&g_cur[ii[e]], 1);
        g_dst[p] = jj[e];
    }
}

// build concatenated weight matrix [W0 | W1], zero-pad row 127
__global__ void k_wcat(const float* __restrict__ W) {
    int t = blockIdx.x * blockDim.x + threadIdx.x;  // 0..16383
    int o = t >> 7;
    int c = t & 127;
    if (o < OO) {
        g_Wcat[o * 256 + c]       = W[(o * 128 + c) * 2 + 0];
        g_Wcat[o * 256 + 128 + c] = W[(o * 128 + c) * 2 + 1];
    } else {
        g_Wcat[o * 256 + c] = 0.0f;
        g_Wcat[o * 256 + 128 + c] = 0.0f;
    }
}

// transpose x[b][c][n] -> xT[b][n][c]; also write U[b][n][c] = cnt_i[n]*xT
__global__ void k_transpose(const float* __restrict__ x) {
    __shared__ float tile[32][33];
    int b = blockIdx.z;
    int c0 = blockIdx.y * 32;
    int n0 = blockIdx.x * 32;
    int tx = threadIdx.x, ty = threadIdx.y;
#pragma unroll
    for (int r = 0; r < 4; r++) {
        int c = c0 + ty + 8 * r;
        tile[ty + 8 * r][tx] = x[((size_t)b * CC + c) * NN + n0 + tx];
    }
    __syncthreads();
#pragma unroll
    for (int r = 0; r < 4; r++) {
        int n = n0 + ty + 8 * r;
        float v = tile[tx][ty + 8 * r];
        float cf = (float)g_cnt[n];
        g_xT[((size_t)b * NN + n) * CC + c0 + tx] = v;
        g_U[((size_t)b * NN + n) * 256 + c0 + tx] = v * cf;
    }
}

// gather: S[b][n][:] = sum over CSR neighbors j of xT[b][j][:]
// one block per n; warp w handles batch w; lane holds a float4 (4 channels)
__global__ void k_gather() {
    int n = blockIdx.x;
    int w = threadIdx.x >> 5;
    int lane = threadIdx.x & 31;
    int beg = g_off[n], end = g_off[n + 1];
    const float4* base = ((const float4*)g_xT) + (size_t)w * NN * 32;
    float4 acc = make_float4(0.f, 0.f, 0.f, 0.f);
    int k = beg;
    for (; k + 4 <= end; k += 4) {
        int j0 = g_dst[k + 0];
        int j1 = g_dst[k + 1];
        int j2 = g_dst[k + 2];
        int j3 = g_dst[k + 3];
        float4 v0 = base[(size_t)j0 * 32 + lane];
        float4 v1 = base[(size_t)j1 * 32 + lane];
        float4 v2 = base[(size_t)j2 * 32 + lane];
        float4 v3 = base[(size_t)j3 * 32 + lane];
        acc.x += (v0.x + v1.x) + (v2.x + v3.x);
        acc.y += (v0.y + v1.y) + (v2.y + v3.y);
        acc.z += (v0.z + v1.z) + (v2.z + v3.z);
        acc.w += (v0.w + v1.w) + (v2.w + v3.w);
    }
    for (; k < end; k++) {
        int j = g_dst[k];
        float4 v = base[(size_t)j * 32 + lane];
        acc.x += v.x; acc.y += v.y; acc.z += v.z; acc.w += v.w;
    }
    ((float4*)(g_U + ((size_t)w * NN + n) * 256 + 128))[lane] = acc;
}

// GEMM: y[b][o][n] = (sum_k U[b][n][k]*Wcat[o][k] + cnt[n]*bias[o]) / max(deg[n],1)
// channel 127 = deg[n]. BM=64 (n), all 128 o per block, K=256, BK=16, 256 thr.
// thread: tx=tid&15 -> 4 consecutive n; ty=tid>>4 -> 8 consecutive o.
__global__ void __launch_bounds__(256) k_gemm(const float* __restrict__ bias,
                                              float* __restrict__ out) {
    __shared__ __align__(16) float As[16][64];
    __shared__ __align__(16) float Bs[16][128];
    int b = blockIdx.y;
    int n0 = blockIdx.x * 64;
    int tid = threadIdx.x;
    int tx = tid & 15;
    int ty = tid >> 4;

    unsigned long long acc[4][4];
#pragma unroll
    for (int i = 0; i < 4; i++)
#pragma unroll
        for (int p = 0; p < 4; p++) acc[i][p] = 0ull;

    const float* Ub = g_U + ((size_t)b * NN + n0) * 256;

    for (int kk = 0; kk < 256; kk += 16) {
        // load A tile (transposed into As[k][m]) -- conflict-free STS.32
        {
            int m = tid & 63;
            int kq = tid >> 6;
            float4 v = *(const float4*)(Ub + (size_t)m * 256 + kk + kq * 4);
            As[kq * 4 + 0][m] = v.x;
            As[kq * 4 + 1][m] = v.y;
            As[kq * 4 + 2][m] = v.z;
            As[kq * 4 + 3][m] = v.w;
        }
        // load B tile (Wcat transposed into Bs[k][o])
#pragma unroll
        for (int r = 0; r < 2; r++) {
            int idx = tid + r * 256;
            int o = idx & 127;
            int kq = idx >> 7;
            float4 v = *(const float4*)(g_Wcat + o * 256 + kk + kq * 4);
            Bs[kq * 4 + 0][o] = v.x;
            Bs[kq * 4 + 1][o] = v.y;
            Bs[kq * 4 + 2][o] = v.z;
            Bs[kq * 4 + 3][o] = v.w;
        }
        __syncthreads();
#pragma unroll
        for (int k = 0; k < 16; k++) {
            float4 av = *(const float4*)&As[k][tx * 4];
            ulonglong2 bv0 = *(const ulonglong2*)&Bs[k][ty * 8];
            ulonglong2 bv1 = *(const ulonglong2*)&Bs[k][ty * 8 + 4];
            unsigned long long a0 = rep2(av.x);
            unsigned long long a1 = rep2(av.y);
            unsigned long long a2 = rep2(av.z);
            unsigned long long a3 = rep2(av.w);
            fma2(acc[0][0], a0, bv0.x); fma2(acc[0][1], a0, bv0.y);
            fma2(acc[0][2], a0, bv1.x); fma2(acc[0][3], a0, bv1.y);
            fma2(acc[1][0], a1, bv0.x); fma2(acc[1][1], a1, bv0.y);
            fma2(acc[1][2], a1, bv1.x); fma2(acc[1][3], a1, bv1.y);
            fma2(acc[2][0], a2, bv0.x); fma2(acc[2][1], a2, bv0.y);
            fma2(acc[2][2], a2, bv1.x); fma2(acc[2][3], a2, bv1.y);
            fma2(acc[3][0], a3, bv0.x); fma2(acc[3][1], a3, bv0.y);
            fma2(acc[3][2], a3, bv1.x); fma2(acc[3][3], a3, bv1.y);
        }
        __syncthreads();
    }

    // epilogue
    float f[4][8];
#pragma unroll
    for (int i = 0; i < 4; i++)
#pragma unroll
        for (int p = 0; p < 4; p++) {
            float2 u = unpack2(acc[i][p]);
            f[i][2 * p] = u.x;
            f[i][2 * p + 1] = u.y;
        }

    int nn0 = n0 + tx * 4;
    float inv[4], cf[4], dg[4];
#pragma unroll
    for (int i = 0; i < 4; i++) {
        int d = g_deg[nn0 + i];
        dg[i] = (float)d;
        inv[i] = 1.0f / (float)(d > 0 ? d : 1);
        cf[i] = (float)g_cnt[nn0 + i];
    }
#pragma unroll
    for (int p = 0; p < 8; p++) {
        int o = ty * 8 + p;
        float bi = (o < OO) ? bias[o] : 0.0f;
        float4 sv;
        if (o < OO) {
            sv.x = (f[0][p] + cf[0] * bi) * inv[0];
            sv.y = (f[1][p] + cf[1] * bi) * inv[1];
            sv.z = (f[2][p] + cf[2] * bi) * inv[2];
            sv.w = (f[3][p] + cf[3] * bi) * inv[3];
        } else {
            sv.x = dg[0]; sv.y = dg[1]; sv.z = dg[2]; sv.w = dg[3];
        }
        *(float4*)&out[((size_t)(b * 128 + o)) * NN + nn0] = sv;
    }
}

// ---------------- launch ----------------
extern "C" void kernel_launch(void* const* d_in, const int* in_sizes, int n_in,
                              void* d_out, int out_size) {
    const float* x = nullptr;
    const float* W = nullptr;
    const float* bias = nullptr;
    const int* ii = nullptr;
    const int* jj = nullptr;
    for (int i = 0; i < n_in; i++) {
        int s = in_sizes[i];
        if (s == BB * CC * NN) x = (const float*)d_in[i];
        else if (s == OO * CC * 2) W = (const float*)d_in[i];
        else if (s == OO) bias = (const float*)d_in[i];
        else if (s == EN) {
            if (!ii) ii = (const int*)d_in[i];
            else jj = (const int*)d_in[i];
        }
    }
    float* out = (float*)d_out;

    k_zero<<<32, 256>>>();
    k_hist<<<EN / 256, 256>>>(ii, jj);
    k_scan<<<1, 1024>>>();
    k_csr<<<EN / 256, 256>>>(ii, jj);
    k_wcat<<<64, 256>>>(W);
    k_transpose<<<dim3(NN / 32, CC / 32, BB), dim3(32, 8)>>>(x);
    k_gather<<<NN, 128>>>();
    k_gemm<<<dim3(NN / 64, BB), 256>>>(bias, out);
}

// round 5
// speedup vs baseline: 1.0673x; 1.0585x over previous
#include <cuda_runtime.h>
#include <cuda_fp16.h>

#define EN 131072
#define NN 4096
#define BB 4
#define CC 128
#define OO 127

// ---------------- scratch (device globals; no allocation) ----------------
__device__ __half g_xTh[(size_t)BB * NN * CC];  // fp16 x^T [b][n][c] (4 MB)
__device__ float  g_WT[256 * 128];              // WT[k][o] k-major (128 KB)
__device__ int    g_cnt[NN];
__device__ int    g_deg[NN];
__device__ int    g_cur[NN];
__device__ int    g_off[NN + 1];
__device__ int    g_dst[EN];

// ---------------- packed f32x2 helpers ----------------
__device__ __forceinline__ unsigned long long rep2(float a) {
    unsigned long long r;
    asm("mov.b64 %0, {%1, %1};" : "=l"(r) : "f"(a));
    return r;
}
__device__ __forceinline__ void fma2(unsigned long long& d,
                                     unsigned long long a,
                                     unsigned long long b) {
    asm("fma.rn.f32x2 %0, %1, %2, %0;" : "+l"(d) : "l"(a), "l"(b));
}
__device__ __forceinline__ float2 unpack2(unsigned long long v) {
    float2 r;
    asm("mov.b64 {%0, %1}, %2;" : "=f"(r.x), "=f"(r.y) : "l"(v));
    return r;
}

// ---------------- small kernels ----------------
__global__ void k_zero() {
    int t = blockIdx.x * blockDim.x + threadIdx.x;  // 8192
    if (t < NN) g_cnt[t] = 0;
    else g_deg[t - NN] = 0;
}

__global__ void k_hist(const int4* __restrict__ ii, const int4* __restrict__ jj) {
    int t = blockIdx.x * blockDim.x + threadIdx.x;  // EN/4
    int4 a = ii[t];
    int4 c = jj[t];
    atomicAdd(&g_cnt[a.x], 1); atomicAdd(&g_cnt[a.y], 1);
    atomicAdd(&g_cnt[a.z], 1); atomicAdd(&g_cnt[a.w], 1);
    atomicAdd(&g_deg[c.x], 1); atomicAdd(&g_deg[c.y], 1);
    atomicAdd(&g_deg[c.z], 1); atomicAdd(&g_deg[c.w], 1);
}

__global__ void k_scan() {
    __shared__ int sm[1024];
    int tid = threadIdx.x;
    int v0 = g_cnt[4 * tid + 0];
    int v1 = g_cnt[4 * tid + 1];
    int v2 = g_cnt[4 * tid + 2];
    int v3 = g_cnt[4 * tid + 3];
    sm[tid] = v0 + v1 + v2 + v3;
    __syncthreads();
    for (int d = 1; d < 1024; d <<= 1) {
        int t = (tid >= d) ? sm[tid - d] : 0;
        __syncthreads();
        sm[tid] += t;
        __syncthreads();
    }
    int base = tid ? sm[tid - 1] : 0;
    int o0 = base, o1 = base + v0, o2 = o1 + v1, o3 = o2 + v2;
    g_off[4 * tid + 0] = o0;  g_cur[4 * tid + 0] = o0;
    g_off[4 * tid + 1] = o1;  g_cur[4 * tid + 1] = o1;
    g_off[4 * tid + 2] = o2;  g_cur[4 * tid + 2] = o2;
    g_off[4 * tid + 3] = o3;  g_cur[4 * tid + 3] = o3;
    if (tid == 1023) g_off[NN] = sm[1023];
}

__global__ void k_csr(const int4* __restrict__ ii, const int4* __restrict__ jj) {
    int t = blockIdx.x * blockDim.x + threadIdx.x;  // EN/4
    int4 a = ii[t];
    int4 v = jj[t];
    int p0 = atomicAdd(&g_cur[a.x], 1);
    int p1 = atomicAdd(&g_cur[a.y], 1);
    int p2 = atomicAdd(&g_cur[a.z], 1);
    int p3 = atomicAdd(&g_cur[a.w], 1);
    g_dst[p0] = v.x; g_dst[p1] = v.y; g_dst[p2] = v.z; g_dst[p3] = v.w;
}

// transpose x[b][c][n] -> fp16 xTh[b][n][c]  +  build WT[k][o]
__global__ void k_prep(const float* __restrict__ x, const float* __restrict__ W) {
    if (blockIdx.x < 2048) {
        __shared__ float tile[32][33];
        const int bt = blockIdx.x;
        const int b = bt >> 9;
        const int c0 = ((bt >> 7) & 3) * 32;
        const int n0 = (bt & 127) * 32;
        const int tx = threadIdx.x & 31, ty = threadIdx.x >> 5;
#pragma unroll
        for (int r = 0; r < 4; r++)
            tile[ty + 8 * r][tx] =
                x[((size_t)(b * CC + c0 + ty + 8 * r)) * NN + n0 + tx];
        __syncthreads();
        __half2* dst = reinterpret_cast<__half2*>(g_xTh);
#pragma unroll
        for (int i = 0; i < 2; i++) {
            int id = threadIdx.x + 256 * i;
            int c2 = id & 15, nl = id >> 4;
            __half2 h = __floats2half2_rn(tile[2 * c2][nl], tile[2 * c2 + 1][nl]);
            dst[((size_t)(b * NN + n0 + nl)) * 64 + (c0 >> 1) + c2] = h;
        }
    } else {
        int bw = blockIdx.x - 2048;  // 16 blocks
#pragma unroll
        for (int i = 0; i < 8; i++) {
            int idx = bw * 256 + threadIdx.x + 4096 * i;  // [0, 32768)
            int o = idx & 127, k = idx >> 7;
            float v = 0.0f;
            if (o < OO) v = W[(o * CC + (k & 127)) * 2 + (k >> 7)];
            g_WT[k * 128 + o] = v;
        }
    }
}

// ---------------- fused gather + GEMM ----------------
__device__ __forceinline__ void accum8(float* a, uint4 v) {
    float2 t0 = __half22float2(*reinterpret_cast<const __half2*>(&v.x));
    float2 t1 = __half22float2(*reinterpret_cast<const __half2*>(&v.y));
    float2 t2 = __half22float2(*reinterpret_cast<const __half2*>(&v.z));
    float2 t3 = __half22float2(*reinterpret_cast<const __half2*>(&v.w));
    a[0] += t0.x; a[1] += t0.y; a[2] += t1.x; a[3] += t1.y;
    a[4] += t2.x; a[5] += t2.y; a[6] += t3.x; a[7] += t3.y;
}

#define FMAS(ACC)                                                              \
    {                                                                          \
        unsigned long long a0 = rep2(av.x), a1 = rep2(av.y),                   \
                           a2 = rep2(av.z), a3 = rep2(av.w);                   \
        fma2(ACC[0][0], a0, bv0.x); fma2(ACC[0][1], a0, bv0.y);                \
        fma2(ACC[0][2], a0, bv1.x); fma2(ACC[0][3], a0, bv1.y);                \
        fma2(ACC[1][0], a1, bv0.x); fma2(ACC[1][1], a1, bv0.y);                \
        fma2(ACC[1][2], a1, bv1.x); fma2(ACC[1][3], a1, bv1.y);                \
        fma2(ACC[2][0], a2, bv0.x); fma2(ACC[2][1], a2, bv0.y);                \
        fma2(ACC[2][2], a2, bv1.x); fma2(ACC[2][3], a2, bv1.y);                \
        fma2(ACC[3][0], a3, bv0.x); fma2(ACC[3][1], a3, bv0.y);                \
        fma2(ACC[3][2], a3, bv1.x); fma2(ACC[3][3], a3, bv1.y);                \
    }

// block = (64 n-rows, one batch). K=256: k<128 from cnt*x (As), k>=128 from
// gathered S (S_s). Swizzle: logical m-group g of channel k stored at
// physical group g ^ ((k>>3)&15).
__global__ void __launch_bounds__(256, 2)
k_fused(const float* __restrict__ x, const float* __restrict__ bias,
        float* __restrict__ out) {
    __shared__ __align__(16) float S_s[8192];  // 128 k x 64 m (swizzled)
    __shared__ __align__(16) float Bs[2048];   // 16 k x 128 o
    __shared__ __align__(16) float As[1024];   // 16 k x 64 m (swizzled)

    const int b   = blockIdx.y;
    const int n0  = blockIdx.x * 64;
    const int tid = threadIdx.x;
    const int w   = tid >> 5;
    const int l   = tid & 31;
    const int lh  = l >> 4;
    const int lc  = l & 15;

    const int tx = tid & 15, ty = tid >> 4;
    const int nb = n0 + tx * 4;
    float cf[4];
#pragma unroll
    for (int i = 0; i < 4; i++) cf[i] = (float)g_cnt[nb + i];

    // ---- phase 1: gather S into S_s (fp16 rows, fp32 accum) ----
    const uint4* xb =
        reinterpret_cast<const uint4*>(g_xTh) + (size_t)b * NN * 16;
    for (int m = w; m < 64; m += 8) {
        const int n = n0 + m;
        const int beg = g_off[n], end = g_off[n + 1];
        float a[8] = {0.f, 0.f, 0.f, 0.f, 0.f, 0.f, 0.f, 0.f};
        int p = beg;
        for (; p + 8 <= end; p += 8) {
            int j0 = g_dst[p + 0 + lh];
            int j1 = g_dst[p + 2 + lh];
            int j2 = g_dst[p + 4 + lh];
            int j3 = g_dst[p + 6 + lh];
            uint4 v0 = __ldcg(xb + (size_t)j0 * 16 + lc);
            uint4 v1 = __ldcg(xb + (size_t)j1 * 16 + lc);
            uint4 v2 = __ldcg(xb + (size_t)j2 * 16 + lc);
            uint4 v3 = __ldcg(xb + (size_t)j3 * 16 + lc);
            accum8(a, v0); accum8(a, v1); accum8(a, v2); accum8(a, v3);
        }
        for (; p < end; p += 2) {
            if (lh == 0 || end - p > 1) {
                int j = g_dst[p + lh];
                uint4 v = __ldcg(xb + (size_t)j * 16 + lc);
                accum8(a, v);
            }
        }
#pragma unroll
        for (int q = 0; q < 8; q++)
            a[q] += __shfl_down_sync(0xffffffffu, a[q], 16);
        if (lh == 0) {
            // channel k' = lc*8+q -> (k'>>3)&15 == lc
            const int col = ((((m >> 2) ^ lc) << 2) + (m & 3));
#pragma unroll
            for (int q = 0; q < 8; q++) S_s[(lc * 8 + q) * 64 + col] = a[q];
        }
    }

    // ---- stage slice 0 (A from x scaled by cnt; B from WT) ----
    const int bk0 = tid >> 5, bo0 = (tid & 31) << 2, bk1 = bk0 + 8;
    const int ak = tid >> 4, am4 = tid & 15;
    {
        float4 rb0 = *reinterpret_cast<const float4*>(&g_WT[bk0 * 128 + bo0]);
        float4 rb1 = *reinterpret_cast<const float4*>(&g_WT[bk1 * 128 + bo0]);
        float4 ra = *reinterpret_cast<const float4*>(
            &x[((size_t)(b * CC + ak)) * NN + n0 + am4 * 4]);
        ra.x *= cf[0]; ra.y *= cf[1]; ra.z *= cf[2]; ra.w *= cf[3];
        *reinterpret_cast<float4*>(&Bs[bk0 * 128 + bo0]) = rb0;
        *reinterpret_cast<float4*>(&Bs[bk1 * 128 + bo0]) = rb1;
        const int sw0 = (ak >> 3) & 15;
        *reinterpret_cast<float4*>(&As[ak * 64 + ((am4 ^ sw0) << 2)]) = ra;
    }
    __syncthreads();

    // ---- phase 2: GEMM over K=256 ----
    unsigned long long acc[4][4];
#pragma unroll
    for (int i = 0; i < 4; i++)
#pragma unroll
        for (int p = 0; p < 4; p++) acc[i][p] = 0ull;

    for (int s = 0; s < 16; s++) {
        float4 rb0, rb1, ra;
        const bool preB = (s < 15);
        const bool preA = (s + 1 < 8);
        if (preB) {
            rb0 = *reinterpret_cast<const float4*>(
                &g_WT[((s + 1) * 16 + bk0) * 128 + bo0]);
            rb1 = *reinterpret_cast<const float4*>(
                &g_WT[((s + 1) * 16 + bk1) * 128 + bo0]);
        }
        if (preA) {
            ra = *reinterpret_cast<const float4*>(
                &x[((size_t)(b * CC + (s + 1) * 16 + ak)) * NN + n0 + am4 * 4]);
            ra.x *= cf[0]; ra.y *= cf[1]; ra.z *= cf[2]; ra.w *= cf[3];
        }
        if (s < 8) {
#pragma unroll
            for (int kl = 0; kl < 16; kl++) {
                const int sw = ((s * 16 + kl) >> 3) & 15;
                float4 av = *reinterpret_cast<const float4*>(
                    &As[kl * 64 + ((tx ^ sw) << 2)]);
                ulonglong2 bv0 =
                    *reinterpret_cast<const ulonglong2*>(&Bs[kl * 128 + ty * 8]);
                ulonglong2 bv1 = *reinterpret_cast<const ulonglong2*>(
                    &Bs[kl * 128 + ty * 8 + 4]);
                FMAS(acc);
            }
        } else {
#pragma unroll
            for (int kl = 0; kl < 16; kl++) {
                const int kp = (s - 8) * 16 + kl;
                const int sw = (kp >> 3) & 15;
                float4 av = *reinterpret_cast<const float4*>(
                    &S_s[kp * 64 + ((tx ^ sw) << 2)]);
                ulonglong2 bv0 =
                    *reinterpret_cast<const ulonglong2*>(&Bs[kl * 128 + ty * 8]);
                ulonglong2 bv1 = *reinterpret_cast<const ulonglong2*>(
                    &Bs[kl * 128 + ty * 8 + 4]);
                FMAS(acc);
            }
        }
        if (preB) {
            __syncthreads();
            *reinterpret_cast<float4*>(&Bs[bk0 * 128 + bo0]) = rb0;
            *reinterpret_cast<float4*>(&Bs[bk1 * 128 + bo0]) = rb1;
            if (preA) {
                const int swn = (((s + 1) * 16 + ak) >> 3) & 15;
                *reinterpret_cast<float4*>(
                    &As[ak * 64 + ((am4 ^ swn) << 2)]) = ra;
            }
            __syncthreads();
        }
    }

    // ---- epilogue: out = (acc + cnt*bias) / max(deg,1); row 127 = deg ----
    float f[4][8];
#pragma unroll
    for (int i = 0; i < 4; i++)
#pragma unroll
        for (int p = 0; p < 4; p++) {
            float2 u = unpack2(acc[i][p]);
            f[i][2 * p] = u.x;
            f[i][2 * p + 1] = u.y;
        }
    float dg[4], inv[4];
#pragma unroll
    for (int i = 0; i < 4; i++) {
        int d = g_deg[nb + i];
        dg[i] = (float)d;
        inv[i] = 1.0f / (float)(d > 0 ? d : 1);
    }
#pragma unroll
    for (int p = 0; p < 8; p++) {
        const int o = ty * 8 + p;
        float4 sv;
        if (o < OO) {
            float bi = bias[o];
            sv.x = (f[0][p] + cf[0] * bi) * inv[0];
            sv.y = (f[1][p] + cf[1] * bi) * inv[1];
            sv.z = (f[2][p] + cf[2] * bi) * inv[2];
            sv.w = (f[3][p] + cf[3] * bi) * inv[3];
        } else {
            sv.x = dg[0]; sv.y = dg[1]; sv.z = dg[2]; sv.w = dg[3];
        }
        *reinterpret_cast<float4*>(&out[((size_t)(b * 128 + o)) * NN + nb]) = sv;
    }
}

// ---------------- launch ----------------
extern "C" void kernel_launch(void* const* d_in, const int* in_sizes, int n_in,
                              void* d_out, int out_size) {
    const float* x = nullptr;
    const float* W = nullptr;
    const float* bias = nullptr;
    const int* ii = nullptr;
    const int* jj = nullptr;
    for (int i = 0; i < n_in; i++) {
        int s = in_sizes[i];
        if (s == BB * CC * NN) x = (const float*)d_in[i];
        else if (s == OO * CC * 2) W = (const float*)d_in[i];
        else if (s == OO) bias = (const float*)d_in[i];
        else if (s == EN) {
            if (!ii) ii = (const int*)d_in[i];
            else jj = (const int*)d_in[i];
        }
    }
    float* out = (float*)d_out;

    k_zero<<<16, 512>>>();
    k_hist<<<EN / 1024, 256>>>((const int4*)ii, (const int4*)jj);
    k_scan<<<1, 1024>>>();
    k_csr<<<EN / 1024, 256>>>((const int4*)ii, (const int4*)jj);
    k_prep<<<2064, 256>>>(x, W);
    k_fused<<<dim3(NN / 64, BB), 256>>>(x, bias, out);
}

// round 6
// speedup vs baseline: 1.1438x; 1.0717x over previous
#include <cuda_runtime.h>
#include <cuda_fp16.h>

#define EN 131072
#define NN 4096
#define BB 4
#define CC 128
#define OO 127

// ---------------- scratch (device globals; no allocation) ----------------
__device__ __half g_xTh[(size_t)BB * NN * CC];  // fp16 x^T [b][n][c] (4 MB)
__device__ float  g_WT[256 * 128];              // WT[k][o] k-major (128 KB)
__device__ int    g_cnt[NN];
__device__ int    g_deg[NN];
__device__ int    g_cur[NN];
__device__ int    g_off[NN + 1];
__device__ int    g_dst[EN];

// ---------------- packed f32x2 helpers ----------------
__device__ __forceinline__ unsigned long long rep2(float a) {
    unsigned long long r;
    asm("mov.b64 %0, {%1, %1};" : "=l"(r) : "f"(a));
    return r;
}
__device__ __forceinline__ void fma2(unsigned long long& d,
                                     unsigned long long a,
                                     unsigned long long b) {
    asm("fma.rn.f32x2 %0, %1, %2, %0;" : "+l"(d) : "l"(a), "l"(b));
}
__device__ __forceinline__ float2 unpack2(unsigned long long v) {
    float2 r;
    asm("mov.b64 {%0, %1}, %2;" : "=f"(r.x), "=f"(r.y) : "l"(v));
    return r;
}

// ---------------- small kernels ----------------
__global__ void k_zero_cnt() { g_cnt[blockIdx.x * blockDim.x + threadIdx.x] = 0; }
__global__ void k_zero_deg() { g_deg[blockIdx.x * blockDim.x + threadIdx.x] = 0; }

__global__ void k_hist_cnt(const int4* __restrict__ ii) {
    int t = blockIdx.x * blockDim.x + threadIdx.x;
    int4 a = ii[t];
    atomicAdd(&g_cnt[a.x], 1); atomicAdd(&g_cnt[a.y], 1);
    atomicAdd(&g_cnt[a.z], 1); atomicAdd(&g_cnt[a.w], 1);
}
__global__ void k_hist_deg(const int4* __restrict__ jj) {
    int t = blockIdx.x * blockDim.x + threadIdx.x;
    int4 c = jj[t];
    atomicAdd(&g_deg[c.x], 1); atomicAdd(&g_deg[c.y], 1);
    atomicAdd(&g_deg[c.z], 1); atomicAdd(&g_deg[c.w], 1);
}

__global__ void k_scan() {
    __shared__ int sm[1024];
    int tid = threadIdx.x;
    int v0 = g_cnt[4 * tid + 0];
    int v1 = g_cnt[4 * tid + 1];
    int v2 = g_cnt[4 * tid + 2];
    int v3 = g_cnt[4 * tid + 3];
    sm[tid] = v0 + v1 + v2 + v3;
    __syncthreads();
    for (int d = 1; d < 1024; d <<= 1) {
        int t = (tid >= d) ? sm[tid - d] : 0;
        __syncthreads();
        sm[tid] += t;
        __syncthreads();
    }
    int base = tid ? sm[tid - 1] : 0;
    int o0 = base, o1 = base + v0, o2 = o1 + v1, o3 = o2 + v2;
    g_off[4 * tid + 0] = o0;  g_cur[4 * tid + 0] = o0;
    g_off[4 * tid + 1] = o1;  g_cur[4 * tid + 1] = o1;
    g_off[4 * tid + 2] = o2;  g_cur[4 * tid + 2] = o2;
    g_off[4 * tid + 3] = o3;  g_cur[4 * tid + 3] = o3;
    if (tid == 1023) g_off[NN] = sm[1023];
}

__global__ void k_csr(const int4* __restrict__ ii, const int4* __restrict__ jj) {
    int t = blockIdx.x * blockDim.x + threadIdx.x;
    int4 a = ii[t];
    int4 v = jj[t];
    int p0 = atomicAdd(&g_cur[a.x], 1);
    int p1 = atomicAdd(&g_cur[a.y], 1);
    int p2 = atomicAdd(&g_cur[a.z], 1);
    int p3 = atomicAdd(&g_cur[a.w], 1);
    g_dst[p0] = v.x; g_dst[p1] = v.y; g_dst[p2] = v.z; g_dst[p3] = v.w;
}

// transpose x[b][c][n] -> fp16 xTh[b][n][c]  +  build WT[k][o]
__global__ void k_prep(const float* __restrict__ x, const float* __restrict__ W) {
    if (blockIdx.x < 2048) {
        __shared__ float tile[32][33];
        const int bt = blockIdx.x;
        const int b = bt >> 9;
        const int c0 = ((bt >> 7) & 3) * 32;
        const int n0 = (bt & 127) * 32;
        const int tx = threadIdx.x & 31, ty = threadIdx.x >> 5;
#pragma unroll
        for (int r = 0; r < 4; r++)
            tile[ty + 8 * r][tx] =
                x[((size_t)(b * CC + c0 + ty + 8 * r)) * NN + n0 + tx];
        __syncthreads();
        __half2* dst = reinterpret_cast<__half2*>(g_xTh);
#pragma unroll
        for (int i = 0; i < 2; i++) {
            int id = threadIdx.x + 256 * i;
            int c2 = id & 15, nl = id >> 4;
            __half2 h = __floats2half2_rn(tile[2 * c2][nl], tile[2 * c2 + 1][nl]);
            dst[((size_t)(b * NN + n0 + nl)) * 64 + (c0 >> 1) + c2] = h;
        }
    } else {
        int bw = blockIdx.x - 2048;  // 16 blocks
#pragma unroll
        for (int i = 0; i < 8; i++) {
            int idx = bw * 256 + threadIdx.x + 4096 * i;
            int o = idx & 127, k = idx >> 7;
            float v = 0.0f;
            if (o < OO) v = W[(o * CC + (k & 127)) * 2 + (k >> 7)];
            g_WT[k * 128 + o] = v;
        }
    }
}

// ---------------- fused gather + GEMM ----------------
__device__ __forceinline__ void accum8(float* a, uint4 v) {
    float2 t0 = __half22float2(*reinterpret_cast<const __half2*>(&v.x));
    float2 t1 = __half22float2(*reinterpret_cast<const __half2*>(&v.y));
    float2 t2 = __half22float2(*reinterpret_cast<const __half2*>(&v.z));
    float2 t3 = __half22float2(*reinterpret_cast<const __half2*>(&v.w));
    a[0] += t0.x; a[1] += t0.y; a[2] += t1.x; a[3] += t1.y;
    a[4] += t2.x; a[5] += t2.y; a[6] += t3.x; a[7] += t3.y;
}

__device__ __forceinline__ void do_gather(int b, int n0, int tid, float* S_s) {
    const int w = tid >> 5;
    const int l = tid & 31;
    const int lh = l >> 4;
    const int lc = l & 15;
    const uint4* xb =
        reinterpret_cast<const uint4*>(g_xTh) + (size_t)b * NN * 16;
    for (int m = w; m < 64; m += 8) {
        const int n = n0 + m;
        const int beg = g_off[n], end = g_off[n + 1];
        float a[8] = {0.f, 0.f, 0.f, 0.f, 0.f, 0.f, 0.f, 0.f};
        int p = beg;
        for (; p + 8 <= end; p += 8) {
            int j0 = g_dst[p + 0 + lh];
            int j1 = g_dst[p + 2 + lh];
            int j2 = g_dst[p + 4 + lh];
            int j3 = g_dst[p + 6 + lh];
            uint4 v0 = __ldcg(xb + (size_t)j0 * 16 + lc);
            uint4 v1 = __ldcg(xb + (size_t)j1 * 16 + lc);
            uint4 v2 = __ldcg(xb + (size_t)j2 * 16 + lc);
            uint4 v3 = __ldcg(xb + (size_t)j3 * 16 + lc);
            accum8(a, v0); accum8(a, v1); accum8(a, v2); accum8(a, v3);
        }
        for (; p < end; p += 2) {
            if (lh == 0 || end - p > 1) {
                int j = g_dst[p + lh];
                uint4 v = __ldcg(xb + (size_t)j * 16 + lc);
                accum8(a, v);
            }
        }
#pragma unroll
        for (int q = 0; q < 8; q++)
            a[q] += __shfl_down_sync(0xffffffffu, a[q], 16);
        if (lh == 0) {
            const int col = ((((m >> 2) ^ lc) << 2) + (m & 3));
#pragma unroll
            for (int q = 0; q < 8; q++) S_s[(lc * 8 + q) * 64 + col] = a[q];
        }
    }
}

#define FMAS(ACC)                                                              \
    {                                                                          \
        unsigned long long a0 = rep2(av.x), a1 = rep2(av.y),                   \
                           a2 = rep2(av.z), a3 = rep2(av.w);                   \
        fma2(ACC[0][0], a0, bv0.x); fma2(ACC[0][1], a0, bv0.y);                \
        fma2(ACC[0][2], a0, bv1.x); fma2(ACC[0][3], a0, bv1.y);                \
        fma2(ACC[1][0], a1, bv0.x); fma2(ACC[1][1], a1, bv0.y);                \
        fma2(ACC[1][2], a1, bv1.x); fma2(ACC[1][3], a1, bv1.y);                \
        fma2(ACC[2][0], a2, bv0.x); fma2(ACC[2][1], a2, bv0.y);                \
        fma2(ACC[2][2], a2, bv1.x); fma2(ACC[2][3], a2, bv1.y);                \
        fma2(ACC[3][0], a3, bv0.x); fma2(ACC[3][1], a3, bv0.y);                \
        fma2(ACC[3][2], a3, bv1.x); fma2(ACC[3][3], a3, bv1.y);                \
    }

// block = (64 n-rows, one batch). K=256: k<128 from cnt*x (As), k>=128 from
// gathered S (S_s). Wave-2 blocks (bid>=148) run GEMM-A before gather so
// co-resident block pairs overlap L2-bound gather with fma-bound GEMM.
__global__ void __launch_bounds__(256, 2)
k_fused(const float* __restrict__ x, const float* __restrict__ bias,
        float* __restrict__ out) {
    __shared__ __align__(16) float S_s[8192];  // 128 k x 64 m (swizzled)
    __shared__ __align__(16) float Bs[2048];   // 16 k x 128 o
    __shared__ __align__(16) float As[1024];   // 16 k x 64 m (swizzled)

    const int b   = blockIdx.y;
    const int n0  = blockIdx.x * 64;
    const int tid = threadIdx.x;
    const int bid = blockIdx.x + (blockIdx.y << 6);
    const bool gemmFirst = (bid >= 148);

    const int tx = tid & 15, ty = tid >> 4;
    const int nb = n0 + tx * 4;
    float cf[4];
#pragma unroll
    for (int i = 0; i < 4; i++) cf[i] = (float)g_cnt[nb + i];

    const int bk0 = tid >> 5, bo0 = (tid & 31) << 2, bk1 = bk0 + 8;
    const int ak = tid >> 4, am4 = tid & 15;

    unsigned long long acc[4][4];
#pragma unroll
    for (int i = 0; i < 4; i++)
#pragma unroll
        for (int p = 0; p < 4; p++) acc[i][p] = 0ull;

    if (!gemmFirst) {
        do_gather(b, n0, tid, S_s);
        __syncthreads();
    }

    // ---- GEMM-A: slices 0..7 (k<128), A = cnt*x streamed from global ----
    {
        float4 rb0 = *reinterpret_cast<const float4*>(&g_WT[bk0 * 128 + bo0]);
        float4 rb1 = *reinterpret_cast<const float4*>(&g_WT[bk1 * 128 + bo0]);
        float4 ra = *reinterpret_cast<const float4*>(
            &x[((size_t)(b * CC + ak)) * NN + n0 + am4 * 4]);
        ra.x *= cf[0]; ra.y *= cf[1]; ra.z *= cf[2]; ra.w *= cf[3];
        *reinterpret_cast<float4*>(&Bs[bk0 * 128 + bo0]) = rb0;
        *reinterpret_cast<float4*>(&Bs[bk1 * 128 + bo0]) = rb1;
        const int sw0 = (ak >> 3) & 15;
        *reinterpret_cast<float4*>(&As[ak * 64 + ((am4 ^ sw0) << 2)]) = ra;
    }
    __syncthreads();
    for (int s = 0; s < 8; s++) {
        float4 rb0, rb1, ra;
        const bool pre = (s < 7);
        if (pre) {
            rb0 = *reinterpret_cast<const float4*>(
                &g_WT[((s + 1) * 16 + bk0) * 128 + bo0]);
            rb1 = *reinterpret_cast<const float4*>(
                &g_WT[((s + 1) * 16 + bk1) * 128 + bo0]);
            ra = *reinterpret_cast<const float4*>(
                &x[((size_t)(b * CC + (s + 1) * 16 + ak)) * NN + n0 + am4 * 4]);
            ra.x *= cf[0]; ra.y *= cf[1]; ra.z *= cf[2]; ra.w *= cf[3];
        }
#pragma unroll
        for (int kl = 0; kl < 16; kl++) {
            const int sw = ((s * 16 + kl) >> 3) & 15;
            float4 av = *reinterpret_cast<const float4*>(
                &As[kl * 64 + ((tx ^ sw) << 2)]);
            ulonglong2 bv0 =
                *reinterpret_cast<const ulonglong2*>(&Bs[kl * 128 + ty * 8]);
            ulonglong2 bv1 =
                *reinterpret_cast<const ulonglong2*>(&Bs[kl * 128 + ty * 8 + 4]);
            FMAS(acc);
        }
        if (pre) {
            __syncthreads();
            *reinterpret_cast<float4*>(&Bs[bk0 * 128 + bo0]) = rb0;
            *reinterpret_cast<float4*>(&Bs[bk1 * 128 + bo0]) = rb1;
            const int swn = (((s + 1) * 16 + ak) >> 3) & 15;
            *reinterpret_cast<float4*>(&As[ak * 64 + ((am4 ^ swn) << 2)]) = ra;
            __syncthreads();
        }
    }

    if (gemmFirst) {
        do_gather(b, n0, tid, S_s);
    }
    __syncthreads();  // all: protect Bs restage + S_s visibility

    // ---- GEMM-S: slices 8..15 (k>=128), A = S_s (already in smem) ----
    {
        float4 rb0 =
            *reinterpret_cast<const float4*>(&g_WT[(128 + bk0) * 128 + bo0]);
        float4 rb1 =
            *reinterpret_cast<const float4*>(&g_WT[(128 + bk1) * 128 + bo0]);
        *reinterpret_cast<float4*>(&Bs[bk0 * 128 + bo0]) = rb0;
        *reinterpret_cast<float4*>(&Bs[bk1 * 128 + bo0]) = rb1;
    }
    __syncthreads();
    for (int s = 0; s < 8; s++) {
        float4 rb0, rb1;
        const bool pre = (s < 7);
        if (pre) {
            rb0 = *reinterpret_cast<const float4*>(
                &g_WT[(128 + (s + 1) * 16 + bk0) * 128 + bo0]);
            rb1 = *reinterpret_cast<const float4*>(
                &g_WT[(128 + (s + 1) * 16 + bk1) * 128 + bo0]);
        }
#pragma unroll
        for (int kl = 0; kl < 16; kl++) {
            const int kp = s * 16 + kl;
            const int sw = (kp >> 3) & 15;
            float4 av = *reinterpret_cast<const float4*>(
                &S_s[kp * 64 + ((tx ^ sw) << 2)]);
            ulonglong2 bv0 =
                *reinterpret_cast<const ulonglong2*>(&Bs[kl * 128 + ty * 8]);
            ulonglong2 bv1 =
                *reinterpret_cast<const ulonglong2*>(&Bs[kl * 128 + ty * 8 + 4]);
            FMAS(acc);
        }
        if (pre) {
            __syncthreads();
            *reinterpret_cast<float4*>(&Bs[bk0 * 128 + bo0]) = rb0;
            *reinterpret_cast<float4*>(&Bs[bk1 * 128 + bo0]) = rb1;
            __syncthreads();
        }
    }

    // ---- epilogue: out = (acc + cnt*bias) / max(deg,1); row 127 = deg ----
    float f[4][8];
#pragma unroll
    for (int i = 0; i < 4; i++)
#pragma unroll
        for (int p = 0; p < 4; p++) {
            float2 u = unpack2(acc[i][p]);
            f[i][2 * p] = u.x;
            f[i][2 * p + 1] = u.y;
        }
    float dg[4], inv[4];
#pragma unroll
    for (int i = 0; i < 4; i++) {
        int d = g_deg[nb + i];
        dg[i] = (float)d;
        inv[i] = 1.0f / (float)(d > 0 ? d : 1);
    }
#pragma unroll
    for (int p = 0; p < 8; p++) {
        const int o = ty * 8 + p;
        float4 sv;
        if (o < OO) {
            float bi = bias[o];
            sv.x = (f[0][p] + cf[0] * bi) * inv[0];
            sv.y = (f[1][p] + cf[1] * bi) * inv[1];
            sv.z = (f[2][p] + cf[2] * bi) * inv[2];
            sv.w = (f[3][p] + cf[3] * bi) * inv[3];
        } else {
            sv.x = dg[0]; sv.y = dg[1]; sv.z = dg[2]; sv.w = dg[3];
        }
        *reinterpret_cast<float4*>(&out[((size_t)(b * 128 + o)) * NN + nb]) = sv;
    }
}

// ---------------- launch (fork/join multi-stream capture) ----------------
extern "C" void kernel_launch(void* const* d_in, const int* in_sizes, int n_in,
                              void* d_out, int out_size) {
    const float* x = nullptr;
    const float* W = nullptr;
    const float* bias = nullptr;
    const int* ii = nullptr;
    const int* jj = nullptr;
    for (int i = 0; i < n_in; i++) {
        int s = in_sizes[i];
        if (s == BB * CC * NN) x = (const float*)d_in[i];
        else if (s == OO * CC * 2) W = (const float*)d_in[i];
        else if (s == OO) bias = (const float*)d_in[i];
        else if (s == EN) {
            if (!ii) ii = (const int*)d_in[i];
            else jj = (const int*)d_in[i];
        }
    }
    float* out = (float*)d_out;

    static cudaStream_t s2 = nullptr;
    static cudaEvent_t evFork = nullptr, evJoin = nullptr;
    if (!s2) {
        cudaStreamCreateWithFlags(&s2, cudaStreamNonBlocking);
        cudaEventCreateWithFlags(&evFork, cudaEventDisableTiming);
        cudaEventCreateWithFlags(&evJoin, cudaEventDisableTiming);
    }

    // fork side branch: deg histogram + prep (independent of cnt/scan/csr)
    cudaEventRecord(evFork, 0);
    cudaStreamWaitEvent(s2, evFork, 0);
    k_zero_deg<<<8, 512, 0, s2>>>();
    k_hist_deg<<<EN / 1024, 256, 0, s2>>>((const int4*)jj);
    k_prep<<<2064, 256, 0, s2>>>(x, W);
    cudaEventRecord(evJoin, s2);

    // main branch: cnt histogram -> scan -> csr
    k_zero_cnt<<<8, 512>>>();
    k_hist_cnt<<<EN / 1024, 256>>>((const int4*)ii);
    k_scan<<<1, 1024>>>();
    k_csr<<<EN / 1024, 256>>>((const int4*)ii, (const int4*)jj);

    // join, then fused gather+GEMM
    cudaStreamWaitEvent(0, evJoin, 0);
    k_fused<<<dim3(NN / 64, BB), 256>>>(x, bias, out);
}